// round 11
// baseline (speedup 1.0000x reference)
#include <cuda_runtime.h>

// Problem constants (fixed by the dataset shapes)
//   scalar_features: (16, 128, 64)   f32
//   distances:       (16, 128, 128, 3) f32
//   w_sv:            (128, 128)      f32   (wa = rows 0..63, wb = rows 64..127)
//   b_sv:            (128,)          f32
//   out:             (16, 128, 128, 3, 128) f32
#define BB 16
#define NN 128
#define FF 64
#define KK 128
#define CC 3
#define ROWS (BB * NN)          // 2048
#define RPB  8                  // rows per gemm block (256 gemm blocks)
#define JSPLIT 4                // j-quarters per row -> expand grid = 8192

// Scratch: pa (bias folded in) and pb, each (2048, 128) f32 = 1 MB.
__device__ float4 g_pa[ROWS * (KK / 4)];
__device__ float4 g_pb[ROWS * (KK / 4)];

// Kernel 1: pa[row,k] = sf[row,:] @ wa[:,k] + bias[k]; pb[row,k] = sf[row,:] @ wb[:,k]
// 256 threads: half 0 (tid<128) computes pa, half 1 computes pb.
// Each thread keeps its 64-entry w-column in registers; block handles RPB rows.
// Launched with PDL (idempotent across graph replays) and ends with an explicit
// PDL trigger so the dependent expand grid unblocks as soon as stores are issued.
__global__ void __launch_bounds__(256) gemm_kernel(
    const float* __restrict__ sf,     // (2048, 64)
    const float* __restrict__ w,      // (128, 128) row-major
    const float* __restrict__ bias,   // (128,)
    float* __restrict__ pa,           // (2048, 128)
    float* __restrict__ pb)           // (2048, 128)
{
    const int k    = threadIdx.x & (KK - 1);
    const int half = threadIdx.x >> 7;           // 0 -> wa/pa, 1 -> wb/pb
    const int row0 = blockIdx.x * RPB;

    __shared__ float sfs[RPB * FF];              // 2 KB

    float wreg[FF];
    const float* wcol = w + (half * FF) * KK + k;
#pragma unroll
    for (int f = 0; f < FF; ++f) wreg[f] = wcol[f * KK];

    for (int i = threadIdx.x; i < RPB * FF; i += 256)
        sfs[i] = sf[row0 * FF + i];
    __syncthreads();

    const float bk = (half == 0) ? bias[k] : 0.0f;
    float* __restrict__ dst = half ? pb : pa;

#pragma unroll
    for (int r = 0; r < RPB; ++r) {
        float acc0 = bk, acc1 = 0.0f;
        const float* s = &sfs[r * FF];
#pragma unroll
        for (int f = 0; f < FF; f += 2) {
            acc0 = fmaf(s[f],     wreg[f],     acc0);
            acc1 = fmaf(s[f + 1], wreg[f + 1], acc1);
        }
        dst[(row0 + r) * KK + k] = acc0 + acc1;
    }

#if __CUDA_ARCH__ >= 900
    cudaTriggerProgrammaticLaunchCompletion();
#endif
}

// Kernel 2: out[b,i,j,c,k] = (pa[b,i,k] + pb[b,j,k]) * dist[b,i,j,c]
// One block per (row, j-quarter); grid = 8192, 48 KB of writes per block.
// 256 threads = 8 warps; warp owns 4 j's within its 32-wide quarter, lane = k4.
// ILP restructure vs R9: ALL four pb LDG.128 and all 12 dist scalars are
// front-batched (MLP=4 on the 128B loads) so load latency is paid once per
// block body; the remainder is a pure burst of 12 coalesced 128B streaming
// stores per thread. PDL prologue prefetches the dist slice, then
// grid-dependency-syncs before touching pa/pb.
__global__ void __launch_bounds__(256) expand_kernel(
    const float*  __restrict__ dist,  // (16,128,128,3)
    const float4* __restrict__ pa4,   // (2048, 32) float4
    const float4* __restrict__ pb4,   // (2048, 32) float4
    float4*       __restrict__ out4)  // (2048, 128, 3, 32) float4
{
    const int row   = blockIdx.x >> 2;             // b*128 + i
    const int j0    = (blockIdx.x & 3) << 5;       // 0, 32, 64, 96
    const int b     = row >> 7;
    const int lane  = threadIdx.x & 31;            // k4
    const int warp  = threadIdx.x >> 5;            // 0..7

    const float* dd = dist + (long)row * (NN * CC) + j0 * CC; // 384B slice

    // Prologue independent of gemm: pull dist slice into L2 while gemm runs.
    if (threadIdx.x < 3)                           // 3 x 128B lines = 384B
        asm volatile("prefetch.global.L2 [%0];" :: "l"(dd + threadIdx.x * 32));

#if __CUDA_ARCH__ >= 900
    cudaGridDependencySynchronize();
#endif

    const float4 s4 = pa4[row * (KK / 4) + lane];        // pa row (bias included)
    const float4* pbb = pb4 + ((long)(b << 7) + j0) * (KK / 4);
    float4* ob = out4 + ((long)row * NN + j0) * (CC * (KK / 4));

    // ---- Front-batched loads: 4 x LDG.128 (pb) + 12 scalar LDG (dist) ----
    float4 p[4];
    float  d[4][3];
#pragma unroll
    for (int t = 0; t < 4; ++t) {
        const int jj = warp + t * 8;
        p[t] = pbb[jj * (KK / 4) + lane];
    }
#pragma unroll
    for (int t = 0; t < 4; ++t) {
        const int jj = warp + t * 8;
        d[t][0] = __ldg(&dd[jj * CC + 0]);
        d[t][1] = __ldg(&dd[jj * CC + 1]);
        d[t][2] = __ldg(&dd[jj * CC + 2]);
    }

    // ---- Compute + store burst: 12 x STG.128 per thread ----
#pragma unroll
    for (int t = 0; t < 4; ++t) {
        const int jj = warp + t * 8;
        float4 v;
        v.x = s4.x + p[t].x;
        v.y = s4.y + p[t].y;
        v.z = s4.z + p[t].z;
        v.w = s4.w + p[t].w;

        float4* o = ob + jj * (CC * (KK / 4)) + lane;
        __stcs(o +  0, make_float4(v.x * d[t][0], v.y * d[t][0], v.z * d[t][0], v.w * d[t][0]));
        __stcs(o + 32, make_float4(v.x * d[t][1], v.y * d[t][1], v.z * d[t][1], v.w * d[t][1]));
        __stcs(o + 64, make_float4(v.x * d[t][2], v.y * d[t][2], v.z * d[t][2], v.w * d[t][2]));
    }
}

extern "C" void kernel_launch(void* const* d_in, const int* in_sizes, int n_in,
                              void* d_out, int out_size)
{
    const float* sf   = (const float*)d_in[0]; // scalar_features
    const float* dist = (const float*)d_in[1]; // distances
    const float* w    = (const float*)d_in[2]; // w_sv
    const float* bias = (const float*)d_in[3]; // b_sv

    float4* pa4;
    float4* pb4;
    cudaGetSymbolAddress((void**)&pa4, g_pa);
    cudaGetSymbolAddress((void**)&pb4, g_pb);

    cudaLaunchAttribute attr[1];
    attr[0].id = cudaLaunchAttributeProgrammaticStreamSerialization;
    attr[0].val.programmaticStreamSerializationAllowed = 1;

    // gemm with PDL: may overlap the tail of the PREVIOUS graph replay's
    // expand. Safe: gemm is idempotent (rewrites identical pa/pb values),
    // and it reads only harness inputs that never change between replays.
    cudaLaunchConfig_t gcfg = {};
    gcfg.gridDim  = dim3(ROWS / RPB);
    gcfg.blockDim = dim3(256);
    gcfg.dynamicSmemBytes = 0;
    gcfg.stream = 0;
    gcfg.attrs = attr;
    gcfg.numAttrs = 1;
    cudaLaunchKernelEx(&gcfg, gemm_kernel, sf, w, bias,
                       (float*)pa4, (float*)pb4);

    // Expand with PDL: may begin while gemm is still running; correctness is
    // preserved by cudaGridDependencySynchronize before pa/pb are read.
    cudaLaunchConfig_t cfg = {};
    cfg.gridDim  = dim3(ROWS * JSPLIT);
    cfg.blockDim = dim3(256);
    cfg.dynamicSmemBytes = 0;
    cfg.stream = 0;
    cfg.attrs = attr;
    cfg.numAttrs = 1;
    cudaLaunchKernelEx(&cfg, expand_kernel, dist,
                       (const float4*)pa4, (const float4*)pb4, (float4*)d_out);
}